// round 9
// baseline (speedup 1.0000x reference)
#include <cuda_runtime.h>

// residual = K3 * (K2 * (K1 * x)), depthwise, per-stage zero padding.
// Register-rolling column-strip kernel:
//   - thread t owns output cols [4t, 4t+4); 128 threads = full 512 width
//   - block sweeps a 64-row band; all intermediates live in registers
//   - K1 = S(x)S - 2 D(x)D  (S=[1,2,1], D=[1,0,1])        -> edge row
//   - K2 = A(x)r0 + B(x)r1  (A=[1,0,-2,0,1], B=[0,1,-2,1,0],
//          r0=[-1,2,-2,2,-1], r1=[2,-6,8,-6,2])           -> H0/H1 + vertical scatter
//   - K3 = [1,-2,1] horizontal at finalize
// Rings: R[5][12] input rows, TA[5][6] tex accumulators; unroll 5 => static indices.

#define IMG   512
#define BAND  64
#define NTH   128

// Load input row ROW (cols cx-4 .. cx+7) into DST[12]; zero outside image.
#define LOADROW(DST, ROW) do {                                                  \
    const float4 _z = make_float4(0.f, 0.f, 0.f, 0.f);                         \
    const bool _rok = ((unsigned)(ROW) < IMG);                                  \
    float4 _va = (_rok && okL) ? *reinterpret_cast<const float4*>(rowp)     : _z; \
    float4 _vb =  _rok         ? *reinterpret_cast<const float4*>(rowp + 4) : _z; \
    float4 _vc = (_rok && okR) ? *reinterpret_cast<const float4*>(rowp + 8) : _z; \
    DST[0]=_va.x; DST[1]=_va.y; DST[2]=_va.z; DST[3]=_va.w;                     \
    DST[4]=_vb.x; DST[5]=_vb.y; DST[6]=_vb.z; DST[7]=_vb.w;                     \
    DST[8]=_vc.x; DST[9]=_vc.y; DST[10]=_vc.z; DST[11]=_vc.w;                   \
    rowp += IMG; } while (0)

// One pipeline step. U = t%5 (literal). TOPS/MIDS: ring slots of rows e-1, e.
// S1..S4 = (U+1..U+4)%5 (literal) for the TA scatter.
#define STEP(U, TOPS, MIDS, S1, S2, S3, S4) do {                                \
    const int t = tt + (U);                                                     \
    const int e = Y0 - 2 + t;              /* edge row index */                 \
    LOADROW(R[U], e + 1);                  /* bot = row e+1 -> slot U */        \
    if ((unsigned)e < IMG && t <= 67) {                                         \
        float SY[12], DY[12];                                                   \
        _Pragma("unroll")                                                       \
        for (int c = 0; c < 12; c++) {                                          \
            float tb = fmaf(1.f, R[TOPS][c], R[U][c]);                          \
            DY[c] = tb;                                                         \
            SY[c] = fmaf(2.f, R[MIDS][c], tb);                                  \
        }                                                                       \
        float E[10];                                                            \
        _Pragma("unroll")                                                       \
        for (int j = 0; j < 10; j++) {                                          \
            float sv = fmaf(2.f, SY[j+1], fmaf(1.f, SY[j], SY[j+2]));           \
            E[j] = fmaf(-2.f, fmaf(1.f, DY[j], DY[j+2]), sv);                   \
        }                                                                       \
        if (tid == 0)          { E[0] = 0.f; E[1] = 0.f; E[2] = 0.f; }          \
        else if (tid == NTH-1) { E[7] = 0.f; E[8] = 0.f; E[9] = 0.f; }          \
        _Pragma("unroll")                                                       \
        for (int c = 0; c < 6; c++) {                                           \
            float s1 = fmaf(1.f, E[c],   E[c+4]);                               \
            float s2 = fmaf(1.f, E[c+1], E[c+3]);                               \
            float H0 = fmaf(-2.f, E[c+2], fmaf( 2.f, s2, -s1));                 \
            float Hh = fmaf( 4.f, E[c+2], fmaf(-3.f, s2,  s1)); /* = H1/2 */    \
            TA[U][c]  = fmaf( 1.f, H0, TA[U][c]);           /* y = e-2 */       \
            TA[S1][c] = fmaf( 2.f, Hh, TA[S1][c]);          /* y = e-1 */       \
            TA[S2][c] = fmaf(-2.f, H0, fmaf(-4.f, Hh, TA[S2][c])); /* y=e */    \
            TA[S3][c] = fmaf( 2.f, Hh, TA[S3][c]);          /* y = e+1 */       \
            TA[S4][c] = fmaf( 1.f, H0, TA[S4][c]);          /* y = e+2 */       \
        }                                                                       \
    }                                                                           \
    { /* finalize output row y = Y0-4+t (slot U), then recycle the slot */      \
        float tv0 = okL ? TA[U][0] : 0.f;   /* tex zero-pad at image cols */    \
        float tv5 = okR ? TA[U][5] : 0.f;                                       \
        if ((unsigned)(t - 4) <= 63u) {                                         \
            float4 o;                                                           \
            o.x = fmaf(-2.f, TA[U][1], fmaf(1.f, tv0,      TA[U][2]));          \
            o.y = fmaf(-2.f, TA[U][2], fmaf(1.f, TA[U][1], TA[U][3]));          \
            o.z = fmaf(-2.f, TA[U][3], fmaf(1.f, TA[U][2], TA[U][4]));          \
            o.w = fmaf(-2.f, TA[U][4], fmaf(1.f, TA[U][3], tv5));               \
            *reinterpret_cast<float4*>(op) = o;                                 \
        }                                                                       \
        op += IMG;                                                              \
        _Pragma("unroll")                                                       \
        for (int c = 0; c < 6; c++) TA[U][c] = 0.f;                             \
    } } while (0)

__global__ __launch_bounds__(NTH, 3)
void residual_feature_kernel(const float* __restrict__ x, float* __restrict__ out)
{
    const int tid = threadIdx.x;
    const int Y0  = blockIdx.x * BAND;
    const long base = (long)blockIdx.y * (IMG * IMG);
    const int cx  = tid * 4;
    const bool okL = (tid != 0);
    const bool okR = (tid != NTH - 1);

    float R[5][12];     // input-row ring (cols cx-4 .. cx+7)
    float TA[5][6];     // tex accumulator ring (cols cx-1 .. cx+4)
#pragma unroll
    for (int s = 0; s < 5; s++)
#pragma unroll
        for (int c = 0; c < 6; c++) TA[s][c] = 0.f;

    const float* rowp = x + base + (long)(Y0 - 3) * IMG + (cx - 4);
    // prime: rows Y0-3 -> slot 3, Y0-2 -> slot 4 (top/mid for first edge row)
    LOADROW(R[3], Y0 - 3);
    LOADROW(R[4], Y0 - 2);

    float* op = out + base + (long)(Y0 - 4) * IMG + cx;

    for (int tt = 0; tt < 70; tt += 5) {
        STEP(0, 3, 4, 1, 2, 3, 4);
        STEP(1, 4, 0, 2, 3, 4, 0);
        STEP(2, 0, 1, 3, 4, 0, 1);
        STEP(3, 1, 2, 4, 0, 1, 2);
        STEP(4, 2, 3, 0, 1, 2, 3);
    }
}

extern "C" void kernel_launch(void* const* d_in, const int* in_sizes, int n_in,
                              void* d_out, int out_size)
{
    const float* x = (const float*)d_in[0];
    float* out = (float*)d_out;
    const int planes = in_sizes[0] / (IMG * IMG);   // 64*3 = 192

    dim3 grid(IMG / BAND, planes);                  // (8, 192)
    residual_feature_kernel<<<grid, NTH>>>(x, out);
}

// round 10
// speedup vs baseline: 1.3510x; 1.3510x over previous
#include <cuda_runtime.h>

// residual = K3 * (K2 * (K1 * x)), depthwise, per-stage zero padding.
// Register-rolling column-strip kernel:
//   - thread t owns output cols [4t, 4t+4); 128 threads = full 512 width
//   - block sweeps a 64-row band; all intermediates live in registers
//   - K1 = S(x)S - 2 D(x)D  (S=[1,2,1], D=[1,0,1])        -> edge row
//   - K2 = A(x)r0 + B(x)r1  (A=[1,0,-2,0,1], B=[0,1,-2,1,0],
//          r0=[-1,2,-2,2,-1], r1=[2,-6,8,-6,2])           -> H0/H1 + vertical scatter
//   - K3 = [1,-2,1] horizontal at finalize
// Rings: R[5][12] input rows, TA[5][6] tex accumulators; unroll 5 => static indices.

#define IMG   512
#define BAND  64
#define NTH   128

// Load input row ROW (cols cx-4 .. cx+7) into DST[12]; zero outside image.
#define LOADROW(DST, ROW) do {                                                  \
    const float4 _z = make_float4(0.f, 0.f, 0.f, 0.f);                         \
    const bool _rok = ((unsigned)(ROW) < IMG);                                  \
    float4 _va = (_rok && okL) ? *reinterpret_cast<const float4*>(rowp)     : _z; \
    float4 _vb =  _rok         ? *reinterpret_cast<const float4*>(rowp + 4) : _z; \
    float4 _vc = (_rok && okR) ? *reinterpret_cast<const float4*>(rowp + 8) : _z; \
    DST[0]=_va.x; DST[1]=_va.y; DST[2]=_va.z; DST[3]=_va.w;                     \
    DST[4]=_vb.x; DST[5]=_vb.y; DST[6]=_vb.z; DST[7]=_vb.w;                     \
    DST[8]=_vc.x; DST[9]=_vc.y; DST[10]=_vc.z; DST[11]=_vc.w;                   \
    rowp += IMG; } while (0)

// One pipeline step. U = t%5 (literal). TOPS/MIDS: ring slots of rows e-1, e.
// S1..S4 = (U+1..U+4)%5 (literal) for the TA scatter.
#define STEP(U, TOPS, MIDS, S1, S2, S3, S4) do {                                \
    const int t = tt + (U);                                                     \
    const int e = Y0 - 2 + t;              /* edge row index */                 \
    LOADROW(R[U], e + 1);                  /* bot = row e+1 -> slot U */        \
    if ((unsigned)e < IMG && t <= 67) {                                         \
        float SY[12], DY[12];                                                   \
        _Pragma("unroll")                                                       \
        for (int c = 0; c < 12; c++) {                                          \
            float tb = fmaf(1.f, R[TOPS][c], R[U][c]);                          \
            DY[c] = tb;                                                         \
            SY[c] = fmaf(2.f, R[MIDS][c], tb);                                  \
        }                                                                       \
        float E[10];                                                            \
        _Pragma("unroll")                                                       \
        for (int j = 0; j < 10; j++) {                                          \
            float sv = fmaf(2.f, SY[j+1], fmaf(1.f, SY[j], SY[j+2]));           \
            E[j] = fmaf(-2.f, fmaf(1.f, DY[j], DY[j+2]), sv);                   \
        }                                                                       \
        if (tid == 0)          { E[0] = 0.f; E[1] = 0.f; E[2] = 0.f; }          \
        else if (tid == NTH-1) { E[7] = 0.f; E[8] = 0.f; E[9] = 0.f; }          \
        _Pragma("unroll")                                                       \
        for (int c = 0; c < 6; c++) {                                           \
            float s1 = fmaf(1.f, E[c],   E[c+4]);                               \
            float s2 = fmaf(1.f, E[c+1], E[c+3]);                               \
            float H0 = fmaf(-2.f, E[c+2], fmaf( 2.f, s2, -s1));                 \
            float Hh = fmaf( 4.f, E[c+2], fmaf(-3.f, s2,  s1)); /* = H1/2 */    \
            TA[U][c]  = fmaf( 1.f, H0, TA[U][c]);           /* y = e-2 */       \
            TA[S1][c] = fmaf( 2.f, Hh, TA[S1][c]);          /* y = e-1 */       \
            TA[S2][c] = fmaf(-2.f, H0, fmaf(-4.f, Hh, TA[S2][c])); /* y=e */    \
            TA[S3][c] = fmaf( 2.f, Hh, TA[S3][c]);          /* y = e+1 */       \
            TA[S4][c] = fmaf( 1.f, H0, TA[S4][c]);          /* y = e+2 */       \
        }                                                                       \
    }                                                                           \
    { /* finalize output row y = Y0-4+t (slot U), then recycle the slot */      \
        float tv0 = okL ? TA[U][0] : 0.f;   /* tex zero-pad at image cols */    \
        float tv5 = okR ? TA[U][5] : 0.f;                                       \
        if ((unsigned)(t - 4) <= 63u) {                                         \
            float4 o;                                                           \
            o.x = fmaf(-2.f, TA[U][1], fmaf(1.f, tv0,      TA[U][2]));          \
            o.y = fmaf(-2.f, TA[U][2], fmaf(1.f, TA[U][1], TA[U][3]));          \
            o.z = fmaf(-2.f, TA[U][3], fmaf(1.f, TA[U][2], TA[U][4]));          \
            o.w = fmaf(-2.f, TA[U][4], fmaf(1.f, TA[U][3], tv5));               \
            *reinterpret_cast<float4*>(op) = o;                                 \
        }                                                                       \
        op += IMG;                                                              \
        _Pragma("unroll")                                                       \
        for (int c = 0; c < 6; c++) TA[U][c] = 0.f;                             \
    } } while (0)

__global__ __launch_bounds__(NTH, 3)
void residual_feature_kernel(const float* __restrict__ x, float* __restrict__ out)
{
    const int tid = threadIdx.x;
    const int Y0  = blockIdx.x * BAND;
    const long base = (long)blockIdx.y * (IMG * IMG);
    const int cx  = tid * 4;
    const bool okL = (tid != 0);
    const bool okR = (tid != NTH - 1);

    float R[5][12];     // input-row ring (cols cx-4 .. cx+7)
    float TA[5][6];     // tex accumulator ring (cols cx-1 .. cx+4)
#pragma unroll
    for (int s = 0; s < 5; s++)
#pragma unroll
        for (int c = 0; c < 6; c++) TA[s][c] = 0.f;

    const float* rowp = x + base + (long)(Y0 - 3) * IMG + (cx - 4);
    // prime: rows Y0-3 -> slot 3, Y0-2 -> slot 4 (top/mid for first edge row)
    LOADROW(R[3], Y0 - 3);
    LOADROW(R[4], Y0 - 2);

    float* op = out + base + (long)(Y0 - 4) * IMG + cx;

    for (int tt = 0; tt < 70; tt += 5) {
        STEP(0, 3, 4, 1, 2, 3, 4);
        STEP(1, 4, 0, 2, 3, 4, 0);
        STEP(2, 0, 1, 3, 4, 0, 1);
        STEP(3, 1, 2, 4, 0, 1, 2);
        STEP(4, 2, 3, 0, 1, 2, 3);
    }
}

extern "C" void kernel_launch(void* const* d_in, const int* in_sizes, int n_in,
                              void* d_out, int out_size)
{
    const float* x = (const float*)d_in[0];
    float* out = (float*)d_out;
    const int planes = in_sizes[0] / (IMG * IMG);   // 64*3 = 192

    dim3 grid(IMG / BAND, planes);                  // (8, 192)
    residual_feature_kernel<<<grid, NTH>>>(x, out);
}

// round 11
// speedup vs baseline: 1.5699x; 1.1620x over previous
#include <cuda_runtime.h>

// residual = K3 * (K2 * (K1 * x)), depthwise, per-stage zero padding.
// Register-rolling column-strip kernel with distance-2 load prefetch:
//   - thread t owns output cols [4t, 4t+4); 128 threads = full 512 width
//   - block sweeps a 32-row band; all intermediates live in registers
//   - step t: LOAD row e+3 (consumed at step t+2), compute edge row e from
//     rows e-1,e,e+1 (loaded >=2 steps ago), scatter K2, finalize row e-2.
//   - K1 = S(x)S - 2 D(x)D  (S=[1,2,1], D=[1,0,1])
//   - K2 = A(x)r0 + B(x)r1  (A=[1,0,-2,0,1], B=[0,1,-2,1,0],
//          r0=[-1,2,-2,2,-1], r1=[2,-6,8,-6,2])
//   - K3 = [1,-2,1] horizontal at finalize
// Input ring R[5][12]: slot(row r) = (r-(Y0-3)) mod 5. Edge e uses slots
// t%5, (t+1)%5, (t+2)%5; load goes to (t+4)%5 (its old row e-2 is dead).

#define IMG   512
#define BAND  32
#define NTH   128

// Load input row ROW (cols cx-4 .. cx+7) into DST[12]; zero outside image.
#define LOADROW(DST, ROW, DOIT) do {                                            \
    const float4 _z = make_float4(0.f, 0.f, 0.f, 0.f);                         \
    const bool _rok = ((unsigned)(ROW) < IMG) && (DOIT);                        \
    float4 _va = (_rok && okL) ? *reinterpret_cast<const float4*>(rowp)     : _z; \
    float4 _vb =  _rok         ? *reinterpret_cast<const float4*>(rowp + 4) : _z; \
    float4 _vc = (_rok && okR) ? *reinterpret_cast<const float4*>(rowp + 8) : _z; \
    DST[0]=_va.x; DST[1]=_va.y; DST[2]=_va.z; DST[3]=_va.w;                     \
    DST[4]=_vb.x; DST[5]=_vb.y; DST[6]=_vb.z; DST[7]=_vb.w;                     \
    DST[8]=_vc.x; DST[9]=_vc.y; DST[10]=_vc.z; DST[11]=_vc.w;                   \
    rowp += IMG; } while (0)

// One pipeline step. U = t%5 (literal), S1..S4 = (U+1..U+4)%5 (literals).
// Rows: e-1 -> R[U], e -> R[S1], e+1 -> R[S2]; prefetch row e+3 -> R[S4].
#define STEP(U, S1, S2, S3, S4) do {                                            \
    const int t = tt + (U);                                                     \
    const int e = Y0 - 2 + t;                                                   \
    LOADROW(R[S4], e + 3, t <= 33);     /* distance-2 prefetch */               \
    if ((unsigned)e < IMG) {                                                    \
        float SY[12], DY[12];                                                   \
        _Pragma("unroll")                                                       \
        for (int c = 0; c < 12; c++) {                                          \
            float tb = fmaf(1.f, R[U][c], R[S2][c]);                            \
            DY[c] = tb;                                                         \
            SY[c] = fmaf(2.f, R[S1][c], tb);                                    \
        }                                                                       \
        float E[10];                                                            \
        _Pragma("unroll")                                                       \
        for (int j = 0; j < 10; j++) {                                          \
            float sv = fmaf(2.f, SY[j+1], fmaf(1.f, SY[j], SY[j+2]));           \
            E[j] = fmaf(-2.f, fmaf(1.f, DY[j], DY[j+2]), sv);                   \
        }                                                                       \
        if (tid == 0)          { E[0] = 0.f; E[1] = 0.f; E[2] = 0.f; }          \
        else if (tid == NTH-1) { E[7] = 0.f; E[8] = 0.f; E[9] = 0.f; }          \
        _Pragma("unroll")                                                       \
        for (int c = 0; c < 6; c++) {                                           \
            float s1 = fmaf(1.f, E[c],   E[c+4]);                               \
            float s2 = fmaf(1.f, E[c+1], E[c+3]);                               \
            float H0 = fmaf(-2.f, E[c+2], fmaf( 2.f, s2, -s1));                 \
            float Hh = fmaf( 4.f, E[c+2], fmaf(-3.f, s2,  s1)); /* = H1/2 */    \
            TA[U][c]  = fmaf( 1.f, H0, TA[U][c]);           /* y = e-2 */       \
            TA[S1][c] = fmaf( 2.f, Hh, TA[S1][c]);          /* y = e-1 */       \
            TA[S2][c] = fmaf(-2.f, H0, fmaf(-4.f, Hh, TA[S2][c])); /* y=e */    \
            TA[S3][c] = fmaf( 2.f, Hh, TA[S3][c]);          /* y = e+1 */       \
            TA[S4][c] = fmaf( 1.f, H0, TA[S4][c]);          /* y = e+2 */       \
        }                                                                       \
    }                                                                           \
    { /* finalize output row y = Y0-4+t (slot U), then recycle the slot */      \
        if (t >= 4) {                                                           \
            float tv0 = okL ? TA[U][0] : 0.f;   /* tex zero-pad */              \
            float tv5 = okR ? TA[U][5] : 0.f;                                   \
            float4 o;                                                           \
            o.x = fmaf(-2.f, TA[U][1], fmaf(1.f, tv0,      TA[U][2]));          \
            o.y = fmaf(-2.f, TA[U][2], fmaf(1.f, TA[U][1], TA[U][3]));          \
            o.z = fmaf(-2.f, TA[U][3], fmaf(1.f, TA[U][2], TA[U][4]));          \
            o.w = fmaf(-2.f, TA[U][4], fmaf(1.f, TA[U][3], tv5));               \
            *reinterpret_cast<float4*>(op) = o;                                 \
        }                                                                       \
        op += IMG;                                                              \
        _Pragma("unroll")                                                       \
        for (int c = 0; c < 6; c++) TA[U][c] = 0.f;                             \
    } } while (0)

__global__ __launch_bounds__(NTH, 4)
void residual_feature_kernel(const float* __restrict__ x, float* __restrict__ out)
{
    const int tid = threadIdx.x;
    const int Y0  = blockIdx.x * BAND;
    const long base = (long)blockIdx.y * (IMG * IMG);
    const int cx  = tid * 4;
    const bool okL = (tid != 0);
    const bool okR = (tid != NTH - 1);

    float R[5][12];     // input-row ring (cols cx-4 .. cx+7)
    float TA[5][6];     // tex accumulator ring (cols cx-1 .. cx+4)
#pragma unroll
    for (int s = 0; s < 5; s++)
#pragma unroll
        for (int c = 0; c < 6; c++) TA[s][c] = 0.f;

    const float* rowp = x + base + (long)(Y0 - 3) * IMG + (cx - 4);
    // prime 4 rows: Y0-3..Y0 -> slots 0..3 (step 0 then prefetches Y0+1 -> slot 4)
    LOADROW(R[0], Y0 - 3, true);
    LOADROW(R[1], Y0 - 2, true);
    LOADROW(R[2], Y0 - 1, true);
    LOADROW(R[3], Y0    , true);

    float* op = out + base + (long)(Y0 - 4) * IMG + cx;

    int tt = 0;
#pragma unroll 1
    for (; tt < 35; tt += 5) {           // t = 0..34
        STEP(0, 1, 2, 3, 4);
        STEP(1, 2, 3, 4, 0);
        STEP(2, 3, 4, 0, 1);
        STEP(3, 4, 0, 1, 2);
        STEP(4, 0, 1, 2, 3);
    }
    // epilogue step t = 35 (tt == 35, U = 0): finalizes output row Y0+31
    STEP(0, 1, 2, 3, 4);
}

extern "C" void kernel_launch(void* const* d_in, const int* in_sizes, int n_in,
                              void* d_out, int out_size)
{
    const float* x = (const float*)d_in[0];
    float* out = (float*)d_out;
    const int planes = in_sizes[0] / (IMG * IMG);   // 64*3 = 192

    dim3 grid(IMG / BAND, planes);                  // (16, 192)
    residual_feature_kernel<<<grid, NTH>>>(x, out);
}

// round 12
// speedup vs baseline: 1.5985x; 1.0182x over previous
#include <cuda_runtime.h>

// residual = K3 * (K2 * (K1 * x)), depthwise, per-stage zero padding.
// Register-rolling column-strip kernel with distance-2 load prefetch:
//   - thread t owns output cols [4t, 4t+4); 128 threads = full 512 width
//   - block sweeps a 32-row band; all intermediates live in registers
//   - step t: LOAD row e+3 (consumed at step t+2), compute edge row e from
//     rows e-1,e,e+1 (loaded >=2 steps ago), scatter K2, finalize row e-2.
//   - K1 = S(x)S - 2 D(x)D  (S=[1,2,1], D=[1,0,1])
//   - K2 = A(x)r0 + B(x)r1  (A=[1,0,-2,0,1], B=[0,1,-2,1,0],
//          r0=[-1,2,-2,2,-1], r1=[2,-6,8,-6,2])
//   - K3 = [1,-2,1] horizontal at finalize
// Input ring R[5][12]: slot(row r) = (r-(Y0-3)) mod 5. Edge e uses slots
// t%5, (t+1)%5, (t+2)%5; load goes to (t+4)%5 (its old row e-2 is dead).

#define IMG   512
#define BAND  32
#define NTH   128

// Load input row ROW (cols cx-4 .. cx+7) into DST[12]; zero outside image.
#define LOADROW(DST, ROW, DOIT) do {                                            \
    const float4 _z = make_float4(0.f, 0.f, 0.f, 0.f);                         \
    const bool _rok = ((unsigned)(ROW) < IMG) && (DOIT);                        \
    float4 _va = (_rok && okL) ? *reinterpret_cast<const float4*>(rowp)     : _z; \
    float4 _vb =  _rok         ? *reinterpret_cast<const float4*>(rowp + 4) : _z; \
    float4 _vc = (_rok && okR) ? *reinterpret_cast<const float4*>(rowp + 8) : _z; \
    DST[0]=_va.x; DST[1]=_va.y; DST[2]=_va.z; DST[3]=_va.w;                     \
    DST[4]=_vb.x; DST[5]=_vb.y; DST[6]=_vb.z; DST[7]=_vb.w;                     \
    DST[8]=_vc.x; DST[9]=_vc.y; DST[10]=_vc.z; DST[11]=_vc.w;                   \
    rowp += IMG; } while (0)

// One pipeline step. U = t%5 (literal), S1..S4 = (U+1..U+4)%5 (literals).
// Rows: e-1 -> R[U], e -> R[S1], e+1 -> R[S2]; prefetch row e+3 -> R[S4].
#define STEP(U, S1, S2, S3, S4) do {                                            \
    const int t = tt + (U);                                                     \
    const int e = Y0 - 2 + t;                                                   \
    LOADROW(R[S4], e + 3, t <= 33);     /* distance-2 prefetch */               \
    if ((unsigned)e < IMG) {                                                    \
        float SY[12], DY[12];                                                   \
        _Pragma("unroll")                                                       \
        for (int c = 0; c < 12; c++) {                                          \
            float tb = fmaf(1.f, R[U][c], R[S2][c]);                            \
            DY[c] = tb;                                                         \
            SY[c] = fmaf(2.f, R[S1][c], tb);                                    \
        }                                                                       \
        float E[10];                                                            \
        _Pragma("unroll")                                                       \
        for (int j = 0; j < 10; j++) {                                          \
            float sv = fmaf(2.f, SY[j+1], fmaf(1.f, SY[j], SY[j+2]));           \
            E[j] = fmaf(-2.f, fmaf(1.f, DY[j], DY[j+2]), sv);                   \
        }                                                                       \
        if (tid == 0)          { E[0] = 0.f; E[1] = 0.f; E[2] = 0.f; }          \
        else if (tid == NTH-1) { E[7] = 0.f; E[8] = 0.f; E[9] = 0.f; }          \
        _Pragma("unroll")                                                       \
        for (int c = 0; c < 6; c++) {                                           \
            float s1 = fmaf(1.f, E[c],   E[c+4]);                               \
            float s2 = fmaf(1.f, E[c+1], E[c+3]);                               \
            float H0 = fmaf(-2.f, E[c+2], fmaf( 2.f, s2, -s1));                 \
            float Hh = fmaf( 4.f, E[c+2], fmaf(-3.f, s2,  s1)); /* = H1/2 */    \
            TA[U][c]  = fmaf( 1.f, H0, TA[U][c]);           /* y = e-2 */       \
            TA[S1][c] = fmaf( 2.f, Hh, TA[S1][c]);          /* y = e-1 */       \
            TA[S2][c] = fmaf(-2.f, H0, fmaf(-4.f, Hh, TA[S2][c])); /* y=e */    \
            TA[S3][c] = fmaf( 2.f, Hh, TA[S3][c]);          /* y = e+1 */       \
            TA[S4][c] = fmaf( 1.f, H0, TA[S4][c]);          /* y = e+2 */       \
        }                                                                       \
    }                                                                           \
    { /* finalize output row y = Y0-4+t (slot U), then recycle the slot */      \
        if (t >= 4) {                                                           \
            float tv0 = okL ? TA[U][0] : 0.f;   /* tex zero-pad */              \
            float tv5 = okR ? TA[U][5] : 0.f;                                   \
            float4 o;                                                           \
            o.x = fmaf(-2.f, TA[U][1], fmaf(1.f, tv0,      TA[U][2]));          \
            o.y = fmaf(-2.f, TA[U][2], fmaf(1.f, TA[U][1], TA[U][3]));          \
            o.z = fmaf(-2.f, TA[U][3], fmaf(1.f, TA[U][2], TA[U][4]));          \
            o.w = fmaf(-2.f, TA[U][4], fmaf(1.f, TA[U][3], tv5));               \
            *reinterpret_cast<float4*>(op) = o;                                 \
        }                                                                       \
        op += IMG;                                                              \
        _Pragma("unroll")                                                       \
        for (int c = 0; c < 6; c++) TA[U][c] = 0.f;                             \
    } } while (0)

__global__ __launch_bounds__(NTH, 4)
void residual_feature_kernel(const float* __restrict__ x, float* __restrict__ out)
{
    const int tid = threadIdx.x;
    const int Y0  = blockIdx.x * BAND;
    const long base = (long)blockIdx.y * (IMG * IMG);
    const int cx  = tid * 4;
    const bool okL = (tid != 0);
    const bool okR = (tid != NTH - 1);

    float R[5][12];     // input-row ring (cols cx-4 .. cx+7)
    float TA[5][6];     // tex accumulator ring (cols cx-1 .. cx+4)
#pragma unroll
    for (int s = 0; s < 5; s++)
#pragma unroll
        for (int c = 0; c < 6; c++) TA[s][c] = 0.f;

    const float* rowp = x + base + (long)(Y0 - 3) * IMG + (cx - 4);
    // prime 4 rows: Y0-3..Y0 -> slots 0..3 (step 0 then prefetches Y0+1 -> slot 4)
    LOADROW(R[0], Y0 - 3, true);
    LOADROW(R[1], Y0 - 2, true);
    LOADROW(R[2], Y0 - 1, true);
    LOADROW(R[3], Y0    , true);

    float* op = out + base + (long)(Y0 - 4) * IMG + cx;

    int tt = 0;
#pragma unroll 1
    for (; tt < 35; tt += 5) {           // t = 0..34
        STEP(0, 1, 2, 3, 4);
        STEP(1, 2, 3, 4, 0);
        STEP(2, 3, 4, 0, 1);
        STEP(3, 4, 0, 1, 2);
        STEP(4, 0, 1, 2, 3);
    }
    // epilogue step t = 35 (tt == 35, U = 0): finalizes output row Y0+31
    STEP(0, 1, 2, 3, 4);
}

extern "C" void kernel_launch(void* const* d_in, const int* in_sizes, int n_in,
                              void* d_out, int out_size)
{
    const float* x = (const float*)d_in[0];
    float* out = (float*)d_out;
    const int planes = in_sizes[0] / (IMG * IMG);   // 64*3 = 192

    dim3 grid(IMG / BAND, planes);                  // (16, 192)
    residual_feature_kernel<<<grid, NTH>>>(x, out);
}

// round 13
// speedup vs baseline: 2.0894x; 1.3071x over previous
#include <cuda_runtime.h>

// residual = K3 * (K2 * (K1 * x)), depthwise, per-stage zero padding.
// Register-rolling column strips, fully unrolled 36-step pipeline.
//  - thread t owns output cols [4t,4t+4); 128 threads = full 512 width
//  - block sweeps a 32-row band; step T computes edge row e=Y0-2+T from
//    input rows e-1,e,e+1 (R ring, 4 slots, distance-1 prefetch of e+2),
//    scatters K2 via rank-2 split into 5 tex accumulators (TA ring, 5 slots),
//    finalizes output row Y0-4+T with K3 = [1,-2,1].
//  - K1 = S(x)S - 2 D(x)D   (S=[1,2,1], D=[1,0,1])
//  - K2 = A(x)r0 + B(x)r1   (A=[1,0,-2,0,1], B=[0,1,-2,1,0],
//         r0=[-1,2,-2,2,-1], r1=[2,-6,8,-6,2])
//  - TA slot for tex row y is FIRST touched as the S4 slot (assignment, no
//    clears). SAFE instantiation adds row-validity checks for the two
//    boundary bands; FAST (middle 14 bands) has none.

#define IMG  512
#define BAND 32
#define NTH  128

// Load input row (Y0-3+REL), cols cx-4..cx+7, into DST[12]; zero outside image.
#define LOADROW(DST, REL) do {                                                  \
    const float4 _z = make_float4(0.f, 0.f, 0.f, 0.f);                          \
    const bool _rok = SAFE ? ((unsigned)(Y0 - 3 + (REL)) < IMG) : true;         \
    const float* _p = ip + (long)(REL) * IMG;                                   \
    float4 _va = (_rok && okL) ? *reinterpret_cast<const float4*>(_p)     : _z; \
    float4 _vb =  _rok         ? *reinterpret_cast<const float4*>(_p + 4) : _z; \
    float4 _vc = (_rok && okR) ? *reinterpret_cast<const float4*>(_p + 8) : _z; \
    DST[0]=_va.x; DST[1]=_va.y; DST[2]=_va.z;  DST[3]=_va.w;                    \
    DST[4]=_vb.x; DST[5]=_vb.y; DST[6]=_vb.z;  DST[7]=_vb.w;                    \
    DST[8]=_vc.x; DST[9]=_vc.y; DST[10]=_vc.z; DST[11]=_vc.w;                   \
} while (0)

// One pipeline step. T literal. TA slots U,S1..S4 = (T..T+4)%5 literals.
// R slots A,B,C = rows e-1,e,e+1 = (T..T+2)%4; D = (T+3)%4 receives row e+2.
#define STEP(T, U, S1, S2, S3, S4, A, B, C, D) do {                             \
    if ((T) <= 34) LOADROW(R[D], (T) + 3);     /* prefetch row e+2 */           \
    const bool _ev = SAFE ? ((unsigned)(Y0 - 2 + (T)) < IMG) : true;            \
    if (_ev) {                                                                  \
        float E[10];                                                            \
        {   /* cols 0..6 -> E[0..4] */                                          \
            float SY[7], DY[7];                                                 \
            _Pragma("unroll")                                                   \
            for (int c = 0; c < 7; c++) {                                       \
                float tb = fmaf(1.f, R[A][c], R[C][c]);                         \
                DY[c] = tb; SY[c] = fmaf(2.f, R[B][c], tb);                     \
            }                                                                   \
            _Pragma("unroll")                                                   \
            for (int j = 0; j < 5; j++) {                                       \
                float sv = fmaf(2.f, SY[j+1], fmaf(1.f, SY[j], SY[j+2]));       \
                E[j] = fmaf(-2.f, fmaf(1.f, DY[j], DY[j+2]), sv);               \
            }                                                                   \
        }                                                                       \
        {   /* cols 5..11 -> E[5..9] */                                         \
            float SY[7], DY[7];                                                 \
            _Pragma("unroll")                                                   \
            for (int c = 0; c < 7; c++) {                                       \
                float tb = fmaf(1.f, R[A][c+5], R[C][c+5]);                     \
                DY[c] = tb; SY[c] = fmaf(2.f, R[B][c+5], tb);                   \
            }                                                                   \
            _Pragma("unroll")                                                   \
            for (int j = 0; j < 5; j++) {                                       \
                float sv = fmaf(2.f, SY[j+1], fmaf(1.f, SY[j], SY[j+2]));       \
                E[j+5] = fmaf(-2.f, fmaf(1.f, DY[j], DY[j+2]), sv);             \
            }                                                                   \
        }                                                                       \
        if (tid == 0)          { E[0] = 0.f; E[1] = 0.f; E[2] = 0.f; }          \
        else if (tid == NTH-1) { E[7] = 0.f; E[8] = 0.f; E[9] = 0.f; }          \
        _Pragma("unroll")                                                       \
        for (int c = 0; c < 6; c++) {                                           \
            float s1 = fmaf(1.f, E[c],   E[c+4]);                               \
            float s2 = fmaf(1.f, E[c+1], E[c+3]);                               \
            float H0 = fmaf(-2.f, E[c+2], fmaf( 2.f, s2, -s1));                 \
            float Hh = fmaf( 4.f, E[c+2], fmaf(-3.f, s2,  s1)); /* H1/2 */      \
            TA[U][c]  = fmaf( 1.f, H0, TA[U][c]);              /* y=e-2 */      \
            TA[S1][c] = fmaf( 2.f, Hh, TA[S1][c]);             /* y=e-1 */      \
            TA[S2][c] = fmaf(-2.f, H0, fmaf(-4.f, Hh, TA[S2][c])); /* y=e */    \
            TA[S3][c] = fmaf( 2.f, Hh, TA[S3][c]);             /* y=e+1 */      \
            TA[S4][c] = H0;            /* first touch of row y=e+2: assign */   \
        }                                                                       \
    } else {                                                                    \
        _Pragma("unroll")                                                       \
        for (int c = 0; c < 6; c++) TA[S4][c] = 0.f;  /* edge row is zero */    \
    }                                                                           \
    if ((T) >= 4) {   /* finalize output row y = Y0-4+T from slot U */          \
        float tv0 = okL ? TA[U][0] : 0.f;   /* tex zero-pad at x edges */       \
        float tv5 = okR ? TA[U][5] : 0.f;                                       \
        float4 o;                                                               \
        o.x = fmaf(-2.f, TA[U][1], fmaf(1.f, tv0,      TA[U][2]));              \
        o.y = fmaf(-2.f, TA[U][2], fmaf(1.f, TA[U][1], TA[U][3]));              \
        o.z = fmaf(-2.f, TA[U][3], fmaf(1.f, TA[U][2], TA[U][4]));              \
        o.w = fmaf(-2.f, TA[U][4], fmaf(1.f, TA[U][3], tv5));                   \
        *reinterpret_cast<float4*>(op + (long)((T) - 4) * IMG) = o;             \
    }                                                                           \
} while (0)

template<bool SAFE>
__global__ __launch_bounds__(NTH, 5)
void rf_kernel(const float* __restrict__ x, float* __restrict__ out)
{
    const int tid = threadIdx.x;
    const int Y0  = SAFE ? (blockIdx.x ? (IMG - BAND) : 0)
                         : (int)(blockIdx.x + 1) * BAND;
    const long base = (long)blockIdx.y * (IMG * IMG);
    const int cx  = tid * 4;
    const bool okL = (tid != 0);
    const bool okR = (tid != NTH - 1);

    float R[4][12];    // input-row ring: slot(rel r) = r % 4, rel = row-(Y0-3)
    float TA[5][6];    // tex accumulator ring: 5 live rows, 6 cols (cx-1..cx+4)

    const float* ip = x + base + (long)(Y0 - 3) * IMG + (cx - 4);
    float* op = out + base + (long)Y0 * IMG + cx;

    // prime rows Y0-3, Y0-2, Y0-1 -> slots 0,1,2 (step 0 prefetches Y0 -> 3)
    LOADROW(R[0], 0);
    LOADROW(R[1], 1);
    LOADROW(R[2], 2);

    STEP( 0, 0,1,2,3,4, 0,1,2,3);
    STEP( 1, 1,2,3,4,0, 1,2,3,0);
    STEP( 2, 2,3,4,0,1, 2,3,0,1);
    STEP( 3, 3,4,0,1,2, 3,0,1,2);
    STEP( 4, 4,0,1,2,3, 0,1,2,3);
    STEP( 5, 0,1,2,3,4, 1,2,3,0);
    STEP( 6, 1,2,3,4,0, 2,3,0,1);
    STEP( 7, 2,3,4,0,1, 3,0,1,2);
    STEP( 8, 3,4,0,1,2, 0,1,2,3);
    STEP( 9, 4,0,1,2,3, 1,2,3,0);
    STEP(10, 0,1,2,3,4, 2,3,0,1);
    STEP(11, 1,2,3,4,0, 3,0,1,2);
    STEP(12, 2,3,4,0,1, 0,1,2,3);
    STEP(13, 3,4,0,1,2, 1,2,3,0);
    STEP(14, 4,0,1,2,3, 2,3,0,1);
    STEP(15, 0,1,2,3,4, 3,0,1,2);
    STEP(16, 1,2,3,4,0, 0,1,2,3);
    STEP(17, 2,3,4,0,1, 1,2,3,0);
    STEP(18, 3,4,0,1,2, 2,3,0,1);
    STEP(19, 4,0,1,2,3, 3,0,1,2);
    STEP(20, 0,1,2,3,4, 0,1,2,3);
    STEP(21, 1,2,3,4,0, 1,2,3,0);
    STEP(22, 2,3,4,0,1, 2,3,0,1);
    STEP(23, 3,4,0,1,2, 3,0,1,2);
    STEP(24, 4,0,1,2,3, 0,1,2,3);
    STEP(25, 0,1,2,3,4, 1,2,3,0);
    STEP(26, 1,2,3,4,0, 2,3,0,1);
    STEP(27, 2,3,4,0,1, 3,0,1,2);
    STEP(28, 3,4,0,1,2, 0,1,2,3);
    STEP(29, 4,0,1,2,3, 1,2,3,0);
    STEP(30, 0,1,2,3,4, 2,3,0,1);
    STEP(31, 1,2,3,4,0, 3,0,1,2);
    STEP(32, 2,3,4,0,1, 0,1,2,3);
    STEP(33, 3,4,0,1,2, 1,2,3,0);
    STEP(34, 4,0,1,2,3, 2,3,0,1);
    STEP(35, 0,1,2,3,4, 3,0,1,2);
}

extern "C" void kernel_launch(void* const* d_in, const int* in_sizes, int n_in,
                              void* d_out, int out_size)
{
    const float* x = (const float*)d_in[0];
    float* out = (float*)d_out;
    const int planes = in_sizes[0] / (IMG * IMG);   // 64*3 = 192

    dim3 gfast(IMG / BAND - 2, planes);             // bands 1..14 (Y0=32..448)
    dim3 gsafe(2, planes);                          // bands 0 and 15
    rf_kernel<false><<<gfast, NTH>>>(x, out);
    rf_kernel<true ><<<gsafe, NTH>>>(x, out);
}

// round 14
// speedup vs baseline: 2.1396x; 1.0240x over previous
#include <cuda_runtime.h>

// residual = K3 * (K2 * (K1 * x)), depthwise, per-stage zero padding.
// Register-rolling column strips, fully unrolled 36-step pipeline, ONE launch.
//  - thread t owns output cols [4t,4t+4); 128 threads = full 512 width
//  - block sweeps a 32-row band; step T computes edge row e=Y0-2+T from
//    input rows e-1,e,e+1 (R ring, 4 slots, distance-1 prefetch of e+2),
//    scatters K2 via rank-2 split into 5 tex accumulators (TA ring, 5 slots),
//    finalizes output row Y0-4+T with K3 = [1,-2,1].
//  - K1 = S(x)S - 2 D(x)D   (S=[1,2,1], D=[1,0,1])
//  - K2 = A(x)r0 + B(x)r1   (A=[1,0,-2,0,1], B=[0,1,-2,1,0],
//         r0=[-1,2,-2,2,-1], r1=[2,-6,8,-6,2])
//  - TA slot for tex row y is FIRST touched as the S4 slot (assignment).
//  - Out-of-image rows can only occur at literal steps:
//      prime REL0..2 and edge T=0,1      -> invalid iff Y0==0       (ntop)
//      prefetch T=32..34 and edge T=34,35 -> invalid iff Y0==480    (nbot)
//    Those steps take uniform runtime bools; all other steps are check-free.

#define IMG  512
#define BAND 32
#define NTH  128

// Load input row (Y0-3+REL), cols cx-4..cx+7, into DST[12]; ROK: row validity.
#define LOADROW(DST, REL, ROK) do {                                             \
    const float4 _z = make_float4(0.f, 0.f, 0.f, 0.f);                         \
    const bool _rok = (ROK);                                                    \
    const float* _p = ip + (long)(REL) * IMG;                                   \
    float4 _va = (_rok && okL) ? *reinterpret_cast<const float4*>(_p)     : _z; \
    float4 _vb =  _rok         ? *reinterpret_cast<const float4*>(_p + 4) : _z; \
    float4 _vc = (_rok && okR) ? *reinterpret_cast<const float4*>(_p + 8) : _z; \
    DST[0]=_va.x; DST[1]=_va.y; DST[2]=_va.z;  DST[3]=_va.w;                    \
    DST[4]=_vb.x; DST[5]=_vb.y; DST[6]=_vb.z;  DST[7]=_vb.w;                    \
    DST[8]=_vc.x; DST[9]=_vc.y; DST[10]=_vc.z; DST[11]=_vc.w;                   \
} while (0)

// One pipeline step. T literal. TA slots U,S1..S4 = (T..T+4)%5 literals.
// R slots A,B,C = rows e-1,e,e+1 = (T..T+2)%4; D = (T+3)%4 receives row e+2.
// PR: prefetch-row validity; EV: edge-row validity (both uniform bools).
#define STEP(T, U, S1, S2, S3, S4, A, B, C, D, PR, EV) do {                     \
    if ((T) <= 34) LOADROW(R[D], (T) + 3, PR);   /* prefetch row e+2 */         \
    if (EV) {                                                                   \
        float E[10];                                                            \
        {   /* cols 0..6 -> E[0..4] */                                          \
            float SY[7], DY[7];                                                 \
            _Pragma("unroll")                                                   \
            for (int c = 0; c < 7; c++) {                                       \
                float tb = fmaf(1.f, R[A][c], R[C][c]);                         \
                DY[c] = tb; SY[c] = fmaf(2.f, R[B][c], tb);                     \
            }                                                                   \
            _Pragma("unroll")                                                   \
            for (int j = 0; j < 5; j++) {                                       \
                float sv = fmaf(2.f, SY[j+1], fmaf(1.f, SY[j], SY[j+2]));       \
                E[j] = fmaf(-2.f, fmaf(1.f, DY[j], DY[j+2]), sv);               \
            }                                                                   \
        }                                                                       \
        {   /* cols 5..11 -> E[5..9] */                                         \
            float SY[7], DY[7];                                                 \
            _Pragma("unroll")                                                   \
            for (int c = 0; c < 7; c++) {                                       \
                float tb = fmaf(1.f, R[A][c+5], R[C][c+5]);                     \
                DY[c] = tb; SY[c] = fmaf(2.f, R[B][c+5], tb);                   \
            }                                                                   \
            _Pragma("unroll")                                                   \
            for (int j = 0; j < 5; j++) {                                       \
                float sv = fmaf(2.f, SY[j+1], fmaf(1.f, SY[j], SY[j+2]));       \
                E[j+5] = fmaf(-2.f, fmaf(1.f, DY[j], DY[j+2]), sv);             \
            }                                                                   \
        }                                                                       \
        if (tid == 0)          { E[0] = 0.f; E[1] = 0.f; E[2] = 0.f; }          \
        else if (tid == NTH-1) { E[7] = 0.f; E[8] = 0.f; E[9] = 0.f; }          \
        _Pragma("unroll")                                                       \
        for (int c = 0; c < 6; c++) {                                           \
            float s1 = fmaf(1.f, E[c],   E[c+4]);                               \
            float s2 = fmaf(1.f, E[c+1], E[c+3]);                               \
            float H0 = fmaf(-2.f, E[c+2], fmaf( 2.f, s2, -s1));                 \
            float Hh = fmaf( 4.f, E[c+2], fmaf(-3.f, s2,  s1)); /* H1/2 */      \
            TA[U][c]  = fmaf( 1.f, H0, TA[U][c]);              /* y=e-2 */      \
            TA[S1][c] = fmaf( 2.f, Hh, TA[S1][c]);             /* y=e-1 */      \
            TA[S2][c] = fmaf(-2.f, H0, fmaf(-4.f, Hh, TA[S2][c])); /* y=e */    \
            TA[S3][c] = fmaf( 2.f, Hh, TA[S3][c]);             /* y=e+1 */      \
            TA[S4][c] = H0;            /* first touch of row y=e+2: assign */   \
        }                                                                       \
    } else {                                                                    \
        _Pragma("unroll")                                                       \
        for (int c = 0; c < 6; c++) TA[S4][c] = 0.f;  /* edge row is zero */    \
    }                                                                           \
    if ((T) >= 4) {   /* finalize output row y = Y0-4+T from slot U */          \
        float tv0 = okL ? TA[U][0] : 0.f;   /* tex zero-pad at x edges */       \
        float tv5 = okR ? TA[U][5] : 0.f;                                       \
        float4 o;                                                               \
        o.x = fmaf(-2.f, TA[U][1], fmaf(1.f, tv0,      TA[U][2]));              \
        o.y = fmaf(-2.f, TA[U][2], fmaf(1.f, TA[U][1], TA[U][3]));              \
        o.z = fmaf(-2.f, TA[U][3], fmaf(1.f, TA[U][2], TA[U][4]));              \
        o.w = fmaf(-2.f, TA[U][4], fmaf(1.f, TA[U][3], tv5));                   \
        *reinterpret_cast<float4*>(op + (long)((T) - 4) * IMG) = o;             \
    }                                                                           \
} while (0)

__global__ __launch_bounds__(NTH, 5)
void rf_kernel(const float* __restrict__ x, float* __restrict__ out)
{
    const int tid = threadIdx.x;
    const int Y0  = (int)blockIdx.x * BAND;
    const long base = (long)blockIdx.y * (IMG * IMG);
    const int cx  = tid * 4;
    const bool okL = (tid != 0);
    const bool okR = (tid != NTH - 1);
    const bool ntop = (Y0 != 0);               // rows above band exist
    const bool nbot = (Y0 != IMG - BAND);      // rows below band exist

    float R[4][12];    // input-row ring: slot(rel r) = r % 4, rel = row-(Y0-3)
    float TA[5][6];    // tex accumulator ring: 5 live rows, 6 cols (cx-1..cx+4)

    const float* ip = x + base + (long)(Y0 - 3) * IMG + (cx - 4);
    float* op = out + base + (long)Y0 * IMG + cx;

    // prime rows Y0-3, Y0-2, Y0-1 -> slots 0,1,2 (step 0 prefetches Y0 -> 3)
    LOADROW(R[0], 0, ntop);
    LOADROW(R[1], 1, ntop);
    LOADROW(R[2], 2, ntop);

    STEP( 0, 0,1,2,3,4, 0,1,2,3, true, ntop);
    STEP( 1, 1,2,3,4,0, 1,2,3,0, true, ntop);
    STEP( 2, 2,3,4,0,1, 2,3,0,1, true, true);
    STEP( 3, 3,4,0,1,2, 3,0,1,2, true, true);
    STEP( 4, 4,0,1,2,3, 0,1,2,3, true, true);
    STEP( 5, 0,1,2,3,4, 1,2,3,0, true, true);
    STEP( 6, 1,2,3,4,0, 2,3,0,1, true, true);
    STEP( 7, 2,3,4,0,1, 3,0,1,2, true, true);
    STEP( 8, 3,4,0,1,2, 0,1,2,3, true, true);
    STEP( 9, 4,0,1,2,3, 1,2,3,0, true, true);
    STEP(10, 0,1,2,3,4, 2,3,0,1, true, true);
    STEP(11, 1,2,3,4,0, 3,0,1,2, true, true);
    STEP(12, 2,3,4,0,1, 0,1,2,3, true, true);
    STEP(13, 3,4,0,1,2, 1,2,3,0, true, true);
    STEP(14, 4,0,1,2,3, 2,3,0,1, true, true);
    STEP(15, 0,1,2,3,4, 3,0,1,2, true, true);
    STEP(16, 1,2,3,4,0, 0,1,2,3, true, true);
    STEP(17, 2,3,4,0,1, 1,2,3,0, true, true);
    STEP(18, 3,4,0,1,2, 2,3,0,1, true, true);
    STEP(19, 4,0,1,2,3, 3,0,1,2, true, true);
    STEP(20, 0,1,2,3,4, 0,1,2,3, true, true);
    STEP(21, 1,2,3,4,0, 1,2,3,0, true, true);
    STEP(22, 2,3,4,0,1, 2,3,0,1, true, true);
    STEP(23, 3,4,0,1,2, 3,0,1,2, true, true);
    STEP(24, 4,0,1,2,3, 0,1,2,3, true, true);
    STEP(25, 0,1,2,3,4, 1,2,3,0, true, true);
    STEP(26, 1,2,3,4,0, 2,3,0,1, true, true);
    STEP(27, 2,3,4,0,1, 3,0,1,2, true, true);
    STEP(28, 3,4,0,1,2, 0,1,2,3, true, true);
    STEP(29, 4,0,1,2,3, 1,2,3,0, true, true);
    STEP(30, 0,1,2,3,4, 2,3,0,1, true, true);
    STEP(31, 1,2,3,4,0, 3,0,1,2, true, true);
    STEP(32, 2,3,4,0,1, 0,1,2,3, nbot, true);
    STEP(33, 3,4,0,1,2, 1,2,3,0, nbot, true);
    STEP(34, 4,0,1,2,3, 2,3,0,1, nbot, nbot);
    STEP(35, 0,1,2,3,4, 3,0,1,2, true, nbot);
}

extern "C" void kernel_launch(void* const* d_in, const int* in_sizes, int n_in,
                              void* d_out, int out_size)
{
    const float* x = (const float*)d_in[0];
    float* out = (float*)d_out;
    const int planes = in_sizes[0] / (IMG * IMG);   // 64*3 = 192

    dim3 grid(IMG / BAND, planes);                  // (16, 192) = 3072 blocks
    rf_kernel<<<grid, NTH>>>(x, out);
}